// round 9
// baseline (speedup 1.0000x reference)
#include <cuda_runtime.h>
#include <cuda_bf16.h>
#include <cstdint>

#define SL 256        // syndrome bit length (fixed for this problem family)
#define NB 8192       // hash-table slots (power of 2, load factor <= 0.5)

// Scratch (no allocation allowed). Zero-init == empty table / flags clear.
// g_sidx[slot]: 0 = empty, else entry_index + 1.
// g_skey[slot]: full 256-bit key for that slot (valid iff sidx != 0).
// Inserts are idempotent across graph replays; flags are reset by the last
// exiting block each run.
__device__ unsigned int g_sidx[NB];
__device__ ulonglong4   g_skey[NB];
__device__ unsigned int g_built;   // # rows inserted this run
__device__ unsigned int g_ready;   // 1 when table complete
__device__ unsigned int g_exit;    // exit counter for replay-safe reset

__device__ __forceinline__ uint64_t mix64(uint64_t x) {
    x ^= x >> 30; x *= 0xBF58476D1CE4E5B9ull;
    x ^= x >> 27; x *= 0x94D049BB133111EBull;
    x ^= x >> 31;
    return x;
}

__device__ __forceinline__ uint64_t fold_hash(uint64_t k0, uint64_t k1,
                                              uint64_t k2, uint64_t k3) {
    return k0 ^ (k1 * 0x9E3779B97F4A7C15ull)
              ^ (k2 * 0xC2B2AE3D27D4EB4Full)
              ^ (k3 * 0x165667B19E3779F9ull);
}

// Warp-cooperative pack of one 256-float binary row into 4 u64 (warp-uniform).
__device__ __forceinline__ void pack_row(const float* __restrict__ row, int lane,
                                         uint64_t& k0, uint64_t& k1,
                                         uint64_t& k2, uint64_t& k3) {
    uint32_t w[8];
#pragma unroll
    for (int i = 0; i < 8; i++) {
        float v = row[i * 32 + lane];                   // coalesced 128B
        w[i] = __ballot_sync(0xffffffffu, v > 0.5f);
    }
    k0 = (uint64_t)w[0] | ((uint64_t)w[1] << 32);
    k1 = (uint64_t)w[2] | ((uint64_t)w[3] << 32);
    k2 = (uint64_t)w[4] | ((uint64_t)w[5] << 32);
    k3 = (uint64_t)w[6] | ((uint64_t)w[7] << 32);
}

// Rare continuation: cluster longer than 32 slots (essentially never at 25% load).
__device__ __noinline__ int probe_more(unsigned b, int lane,
    uint64_t q0, uint64_t q1, uint64_t q2, uint64_t q3)
{
    int best = 0x7fffffff;
    for (;;) {
        unsigned slot = (b + lane) & (NB - 1);
        unsigned s = __ldg(&g_sidx[slot]);
        unsigned empty = __ballot_sync(0xffffffffu, s == 0u);
        int fe = empty ? (__ffs(empty) - 1) : 32;
        if (s != 0u && lane < fe) {
            const ulonglong2* kp = (const ulonglong2*)&g_skey[slot];
            ulonglong2 a = __ldg(kp);
            ulonglong2 c = __ldg(kp + 1);
            if (a.x == q0 && a.y == q1 && c.x == q2 && c.y == q3)
                best = min(best, (int)s - 1);
        }
        if (fe < 32) break;
        b = (b + 32) & (NB - 1);
    }
    return best;
}

// ---------------------------------------------------------------------------
// Fused kernel, single launch.
//  - warps 0..1 of each block insert table rows (2 rows/block, spread chip-wide)
//  - every warp packs its own query + hash (overlaps with build)
//  - per-warp spin on g_ready (set by the LAST inserter, not a grid barrier)
//  - single-hop warp-parallel probe, then float4 value copy / zeros
// All 1024 blocks are co-resident (256 thr, 8 blocks/SM -> 1184 >= 1024),
// so the spin cannot deadlock.
// ---------------------------------------------------------------------------
__global__ __launch_bounds__(256, 8) void fused_kernel(
    const float* __restrict__ syn,
    const float* __restrict__ tk,
    const float* __restrict__ tv,
    float* __restrict__ out,
    int B, int T)
{
    const int lane = threadIdx.x & 31;
    const int wid  = threadIdx.x >> 5;          // 0..7

    // ---------------- Build contribution (warps 0..1) ----------------
    if (wid < 2) {
        for (int row_i = blockIdx.x * 2 + wid; row_i < T; row_i += gridDim.x * 2) {
            uint64_t k0, k1, k2, k3;
            pack_row(tk + (size_t)row_i * SL, lane, k0, k1, k2, k3);
            if (lane == 0) {
                unsigned b = (unsigned)mix64(fold_hash(k0, k1, k2, k3)) & (NB - 1);
                unsigned tag = (unsigned)row_i + 1u;
                for (;;) {
                    unsigned prev = atomicCAS(&g_sidx[b], 0u, tag);
                    if (prev == 0u || prev == tag) break;   // idempotent on replay
                    b = (b + 1) & (NB - 1);
                }
                ulonglong2* kp = (ulonglong2*)&g_skey[b];
                kp[0] = make_ulonglong2(k0, k1);
                kp[1] = make_ulonglong2(k2, k3);
                __threadfence();                    // key visible before count
                unsigned n = atomicAdd(&g_built, 1u);
                if (n == (unsigned)T - 1u) {        // last inserter publishes
                    __threadfence();
                    g_ready = 1u;
                }
            }
        }
    }

    // ---------------- Pack own query + hash (overlaps build) ----------------
    const int q = blockIdx.x * 8 + wid;
    uint64_t q0 = 0, q1 = 0, q2 = 0, q3 = 0;
    unsigned b0 = 0;
    if (q < B) {
        pack_row(syn + (size_t)q * SL, lane, q0, q1, q2, q3);
        b0 = (unsigned)mix64(fold_hash(q0, q1, q2, q3)) & (NB - 1);
    }

    // ---------------- Wait for table completion (per-warp spin) -------------
    if (lane == 0) {
        volatile unsigned* rdy = &g_ready;
        while (*rdy == 0u) __nanosleep(64);
    }
    __syncwarp();
    __threadfence();    // acquire: table stores visible to this warp's loads

    // ---------------- Probe + emit ----------------
    if (q < B) {
        unsigned slot = (b0 + lane) & (NB - 1);
        unsigned s = __ldg(&g_sidx[slot]);

        // Speculative key loads on the first 8 lanes (clusters >8 are rare);
        // issues in parallel with the sidx load since the address only
        // depends on the slot.
        ulonglong2 ka, kc;
        bool spec = (lane < 8);
        if (spec) {
            const ulonglong2* kp = (const ulonglong2*)&g_skey[slot];
            ka = __ldg(kp);
            kc = __ldg(kp + 1);
        }

        unsigned empty = __ballot_sync(0xffffffffu, s == 0u);
        int fe = empty ? (__ffs(empty) - 1) : 32;

        int best = 0x7fffffff;
        if (s != 0u && lane < fe) {
            if (!spec) {   // rare dependent fallback for lanes 8..fe-1
                const ulonglong2* kp = (const ulonglong2*)&g_skey[slot];
                ka = __ldg(kp);
                kc = __ldg(kp + 1);
            }
            if (ka.x == q0 && ka.y == q1 && kc.x == q2 && kc.y == q3)
                best = (int)s - 1;                    // first match = min idx
        }
        if (fe == 32)
            best = min(best, probe_more((b0 + 32) & (NB - 1), lane, q0, q1, q2, q3));

        best = (int)__reduce_min_sync(0xffffffffu, (unsigned)best);

        // Vectorized emit: 256 floats = 64 float4; 2 per lane.
        float4* orow4 = (float4*)(out + (size_t)q * SL);
        if (best != 0x7fffffff) {
            const float4* vr = (const float4*)(tv + (size_t)best * SL);
            float4 a = __ldg(vr + lane);
            float4 c = __ldg(vr + lane + 32);
            orow4[lane]      = a;
            orow4[lane + 32] = c;
        } else {
            float4 z = make_float4(0.f, 0.f, 0.f, 0.f);
            orow4[lane]      = z;
            orow4[lane + 32] = z;
        }
    }

    // ---------------- Replay-safe reset ----------------
    // Each block increments g_exit only after all its warps passed the spin
    // and finished. The last block resets the flags for the next replay.
    __syncthreads();
    if (threadIdx.x == 0) {
        unsigned old = atomicAdd(&g_exit, 1u);
        if (old == gridDim.x - 1u) {
            g_built = 0u;
            g_ready = 0u;
            __threadfence();
            g_exit = 0u;
        }
    }
}

// ---------------------------------------------------------------------------
extern "C" void kernel_launch(void* const* d_in, const int* in_sizes, int n_in,
                              void* d_out, int out_size) {
    const float* syn = (const float*)d_in[0];   // [B, 256]
    const float* tk  = (const float*)d_in[1];   // [T, 256]
    const float* tv  = (const float*)d_in[2];   // [T, 256]
    float* out = (float*)d_out;                 // [B, 256]

    int B = in_sizes[0] / SL;
    int T = in_sizes[1] / SL;

    int blocks = (B + 7) / 8;                   // 1024 for B=8192 (co-resident)
    fused_kernel<<<blocks, 256>>>(syn, tk, tv, out, B, T);
}

// round 10
// speedup vs baseline: 1.5496x; 1.5496x over previous
#include <cuda_runtime.h>
#include <cuda_bf16.h>
#include <cstdint>

#define SL 256        // syndrome bit length (fixed for this problem family)
#define NB 8192       // hash-table slots (power of 2, load factor <= 0.5)

// Scratch (no allocation allowed). Zero-init == empty table.
// g_sidx[slot]: 0 = empty, else entry_index + 1.
// g_skey[slot]: full 256-bit key for that slot (valid iff sidx != 0).
// Inserts are idempotent across graph replays (same keys -> same slots/values).
__device__ unsigned int g_sidx[NB];
__device__ ulonglong4   g_skey[NB];

__device__ __forceinline__ uint64_t mix64(uint64_t x) {
    x ^= x >> 30; x *= 0xBF58476D1CE4E5B9ull;
    x ^= x >> 27; x *= 0x94D049BB133111EBull;
    x ^= x >> 31;
    return x;
}

__device__ __forceinline__ uint64_t fold_hash(uint64_t k0, uint64_t k1,
                                              uint64_t k2, uint64_t k3) {
    return k0 ^ (k1 * 0x9E3779B97F4A7C15ull)
              ^ (k2 * 0xC2B2AE3D27D4EB4Full)
              ^ (k3 * 0x165667B19E3779F9ull);
}

// Warp-cooperative pack of one 256-float binary row into 4 u64 (warp-uniform).
__device__ __forceinline__ void pack_row(const float* __restrict__ row, int lane,
                                         uint64_t& k0, uint64_t& k1,
                                         uint64_t& k2, uint64_t& k3) {
    uint32_t w[8];
#pragma unroll
    for (int i = 0; i < 8; i++) {
        float v = row[i * 32 + lane];                   // coalesced 128B
        w[i] = __ballot_sync(0xffffffffu, v > 0.5f);
    }
    k0 = (uint64_t)w[0] | ((uint64_t)w[1] << 32);
    k1 = (uint64_t)w[2] | ((uint64_t)w[3] << 32);
    k2 = (uint64_t)w[4] | ((uint64_t)w[5] << 32);
    k3 = (uint64_t)w[6] | ((uint64_t)w[7] << 32);
}

// ---------------------------------------------------------------------------
// Kernel 1: build. One warp per table row; insert idx+1 + packed key into the
// slot. Triggers programmatic launch completion as soon as its work is done.
// ---------------------------------------------------------------------------
__global__ __launch_bounds__(256) void build_table_kernel(
    const float* __restrict__ tk, int T)
{
    int row_i = (blockIdx.x * blockDim.x + threadIdx.x) >> 5;
    int lane  = threadIdx.x & 31;

    if (row_i < T) {
        uint64_t k0, k1, k2, k3;
        pack_row(tk + (size_t)row_i * SL, lane, k0, k1, k2, k3);

        if (lane == 0) {
            unsigned b = (unsigned)mix64(fold_hash(k0, k1, k2, k3)) & (NB - 1);
            unsigned tag = (unsigned)row_i + 1u;
            for (;;) {
                unsigned prev = atomicCAS(&g_sidx[b], 0u, tag);
                if (prev == 0u || prev == tag) break;   // idempotent on replay
                b = (b + 1) & (NB - 1);
            }
            ulonglong2* kp = (ulonglong2*)&g_skey[b];
            kp[0] = make_ulonglong2(k0, k1);
            kp[1] = make_ulonglong2(k2, k3);
            __threadfence();    // publish before signaling completion
        }
    }
    // Release PDL dependents as early as possible (fires when all CTAs
    // have triggered or exited).
    cudaTriggerProgrammaticLaunchCompletion();
}

// Rare continuation: cluster longer than 32 slots (essentially never at 25% load).
__device__ __noinline__ int probe_more(unsigned b, int lane,
    uint64_t q0, uint64_t q1, uint64_t q2, uint64_t q3)
{
    int best = 0x7fffffff;
    for (;;) {
        unsigned slot = (b + lane) & (NB - 1);
        unsigned s = __ldg(&g_sidx[slot]);
        unsigned empty = __ballot_sync(0xffffffffu, s == 0u);
        int fe = empty ? (__ffs(empty) - 1) : 32;
        if (s != 0u && lane < fe) {
            const ulonglong2* kp = (const ulonglong2*)&g_skey[slot];
            ulonglong2 a = __ldg(kp);
            ulonglong2 c = __ldg(kp + 1);
            if (a.x == q0 && a.y == q1 && c.x == q2 && c.y == q3)
                best = min(best, (int)s - 1);
        }
        if (fe < 32) break;
        b = (b + 32) & (NB - 1);
    }
    return best;
}

// ---------------------------------------------------------------------------
// Kernel 2: lookup, PDL-overlapped. Packs its query + hash BEFORE
// cudaGridDependencySynchronize(), so the 8MB syndrome read overlaps the
// build kernel. Only the probe + emit wait for the table.
// ---------------------------------------------------------------------------
__global__ __launch_bounds__(256) void lookup_kernel(
    const float* __restrict__ syn,
    const float* __restrict__ tv,
    float* __restrict__ out,
    int B)
{
    const int lane = threadIdx.x & 31;
    const int q = blockIdx.x * (blockDim.x >> 5) + (threadIdx.x >> 5);

    // ---- Independent phase: pack query + hash (overlaps build kernel) ----
    uint64_t q0 = 0, q1 = 0, q2 = 0, q3 = 0;
    unsigned b0 = 0;
    if (q < B) {
        pack_row(syn + (size_t)q * SL, lane, q0, q1, q2, q3);
        b0 = (unsigned)mix64(fold_hash(q0, q1, q2, q3)) & (NB - 1);
    }

    // ---- Wait for the build kernel's results to be visible ----
    cudaGridDependencySynchronize();

    if (q >= B) return;

    // ---- Single-hop warp-parallel probe ----
    unsigned slot = (b0 + lane) & (NB - 1);
    unsigned s = __ldg(&g_sidx[slot]);

    // Speculative key loads on lanes 0..7 (clusters >8 are vanishingly rare);
    // address depends only on the slot, so these issue in parallel with sidx.
    ulonglong2 ka, kc;
    bool spec = (lane < 8);
    if (spec) {
        const ulonglong2* kp = (const ulonglong2*)&g_skey[slot];
        ka = __ldg(kp);
        kc = __ldg(kp + 1);
    }

    unsigned empty = __ballot_sync(0xffffffffu, s == 0u);
    int fe = empty ? (__ffs(empty) - 1) : 32;

    int best = 0x7fffffff;
    if (s != 0u && lane < fe) {
        if (!spec) {   // rare dependent fallback for lanes 8..fe-1
            const ulonglong2* kp = (const ulonglong2*)&g_skey[slot];
            ka = __ldg(kp);
            kc = __ldg(kp + 1);
        }
        if (ka.x == q0 && ka.y == q1 && kc.x == q2 && kc.y == q3)
            best = (int)s - 1;                        // first match = min idx
    }
    if (fe == 32)
        best = min(best, probe_more((b0 + 32) & (NB - 1), lane, q0, q1, q2, q3));

    best = (int)__reduce_min_sync(0xffffffffu, (unsigned)best);

    // ---- Vectorized emit: 256 floats = 64 float4; 2 per lane ----
    float4* orow4 = (float4*)(out + (size_t)q * SL);
    if (best != 0x7fffffff) {
        const float4* vr = (const float4*)(tv + (size_t)best * SL);
        float4 a = __ldg(vr + lane);
        float4 c = __ldg(vr + lane + 32);
        orow4[lane]      = a;
        orow4[lane + 32] = c;
    } else {
        float4 z = make_float4(0.f, 0.f, 0.f, 0.f);
        orow4[lane]      = z;
        orow4[lane + 32] = z;
    }
}

// ---------------------------------------------------------------------------
extern "C" void kernel_launch(void* const* d_in, const int* in_sizes, int n_in,
                              void* d_out, int out_size) {
    const float* syn = (const float*)d_in[0];   // [B, 256]
    const float* tk  = (const float*)d_in[1];   // [T, 256]
    const float* tv  = (const float*)d_in[2];   // [T, 256]
    float* out = (float*)d_out;                 // [B, 256]

    int B = in_sizes[0] / SL;
    int T = in_sizes[1] / SL;

    // Build: one warp per row.
    build_table_kernel<<<(T + 7) / 8, 256>>>(tk, T);

    // Lookup: launched with programmatic stream serialization (PDL) so it
    // starts while build runs; it self-synchronizes via
    // cudaGridDependencySynchronize before touching the table.
    cudaLaunchConfig_t cfg = {};
    cfg.gridDim  = dim3((B + 7) / 8, 1, 1);
    cfg.blockDim = dim3(256, 1, 1);
    cfg.dynamicSmemBytes = 0;
    cfg.stream = 0;
    cudaLaunchAttribute attr[1];
    attr[0].id = cudaLaunchAttributeProgrammaticStreamSerialization;
    attr[0].val.programmaticStreamSerializationAllowed = 1;
    cfg.attrs = attr;
    cfg.numAttrs = 1;
    cudaLaunchKernelEx(&cfg, lookup_kernel, syn, tv, out, B);
}

// round 12
// speedup vs baseline: 2.0962x; 1.3528x over previous
#include <cuda_runtime.h>
#include <cuda_bf16.h>
#include <cstdint>

#define SL 256        // syndrome bit length (fixed for this problem family)
#define NB 8192       // hash-table slots (power of 2, load factor <= 0.5)

// Scratch (no allocation allowed). Zero-init == empty table.
// g_sidx[slot]: 0 = empty, else entry_index + 1.
// g_skey[slot]: full 256-bit (permuted-order) key for that slot.
// Inserts are idempotent across graph replays.
__device__ unsigned int g_sidx[NB];
__device__ ulonglong4   g_skey[NB];

__device__ __forceinline__ uint64_t mix64(uint64_t x) {
    x ^= x >> 30; x *= 0xBF58476D1CE4E5B9ull;
    x ^= x >> 27; x *= 0x94D049BB133111EBull;
    x ^= x >> 31;
    return x;
}

__device__ __forceinline__ uint64_t fold_hash(uint64_t k0, uint64_t k1,
                                              uint64_t k2, uint64_t k3) {
    return k0 ^ (k1 * 0x9E3779B97F4A7C15ull)
              ^ (k2 * 0xC2B2AE3D27D4EB4Full)
              ^ (k3 * 0x165667B19E3779F9ull);
}

// Warp-cooperative pack via float4: 2 LDG.128 per lane (MLP_p1=2) + 8 ballots.
// Produces a FIXED bit permutation of the row; build and lookup use the same
// function, so exact-match equality is preserved.
__device__ __forceinline__ void pack_row_f4(const float* __restrict__ row,
                                            int lane,
                                            uint64_t& k0, uint64_t& k1,
                                            uint64_t& k2, uint64_t& k3) {
    const float4* r4 = (const float4*)row;
    float4 a = __ldg(r4 + lane);        // floats [4l .. 4l+3]
    float4 b = __ldg(r4 + lane + 32);   // floats [128+4l .. 128+4l+3]
    const unsigned m = 0xffffffffu;
    uint32_t w0 = __ballot_sync(m, a.x > 0.5f);
    uint32_t w1 = __ballot_sync(m, a.y > 0.5f);
    uint32_t w2 = __ballot_sync(m, a.z > 0.5f);
    uint32_t w3 = __ballot_sync(m, a.w > 0.5f);
    uint32_t w4 = __ballot_sync(m, b.x > 0.5f);
    uint32_t w5 = __ballot_sync(m, b.y > 0.5f);
    uint32_t w6 = __ballot_sync(m, b.z > 0.5f);
    uint32_t w7 = __ballot_sync(m, b.w > 0.5f);
    k0 = (uint64_t)w0 | ((uint64_t)w1 << 32);
    k1 = (uint64_t)w2 | ((uint64_t)w3 << 32);
    k2 = (uint64_t)w4 | ((uint64_t)w5 << 32);
    k3 = (uint64_t)w6 | ((uint64_t)w7 << 32);
}

// ---------------------------------------------------------------------------
// Kernel 1: build. One warp per table row; insert idx+1 + packed key.
// ---------------------------------------------------------------------------
__global__ __launch_bounds__(256) void build_table_kernel(
    const float* __restrict__ tk, int T)
{
    int row_i = (blockIdx.x * blockDim.x + threadIdx.x) >> 5;
    int lane  = threadIdx.x & 31;
    if (row_i >= T) return;

    uint64_t k0, k1, k2, k3;
    pack_row_f4(tk + (size_t)row_i * SL, lane, k0, k1, k2, k3);

    if (lane == 0) {
        unsigned b = (unsigned)mix64(fold_hash(k0, k1, k2, k3)) & (NB - 1);
        unsigned tag = (unsigned)row_i + 1u;
        for (;;) {
            unsigned prev = atomicCAS(&g_sidx[b], 0u, tag);
            if (prev == 0u || prev == tag) break;       // idempotent on replay
            b = (b + 1) & (NB - 1);
        }
        ulonglong2* kp = (ulonglong2*)&g_skey[b];
        kp[0] = make_ulonglong2(k0, k1);
        kp[1] = make_ulonglong2(k2, k3);
    }
}

// Rare continuation: cluster longer than 32 slots (essentially never at 25% load).
__device__ __noinline__ int probe_more(unsigned b, int lane,
    uint64_t q0, uint64_t q1, uint64_t q2, uint64_t q3)
{
    int best = 0x7fffffff;
    for (;;) {
        unsigned slot = (b + lane) & (NB - 1);
        unsigned s = __ldg(&g_sidx[slot]);
        unsigned empty = __ballot_sync(0xffffffffu, s == 0u);
        int fe = empty ? (__ffs(empty) - 1) : 32;
        if (s != 0u && lane < fe) {
            const ulonglong2* kp = (const ulonglong2*)&g_skey[slot];
            ulonglong2 a = __ldg(kp);
            ulonglong2 c = __ldg(kp + 1);
            if (a.x == q0 && a.y == q1 && c.x == q2 && c.y == q3)
                best = min(best, (int)s - 1);
        }
        if (fe < 32) break;
        b = (b + 32) & (NB - 1);
    }
    return best;
}

// ---------------------------------------------------------------------------
// Kernel 2: lookup. One warp per query; 512-thread blocks (16 warps) for
// higher resident-warp count. Single-hop probe: slot-keyed key array lets the
// verify load issue in parallel with the slot-index load.
// ---------------------------------------------------------------------------
__global__ __launch_bounds__(512) void lookup_kernel(
    const float* __restrict__ syn,
    const float* __restrict__ tv,
    float* __restrict__ out,
    int B)
{
    const int lane = threadIdx.x & 31;
    const int q = blockIdx.x * (blockDim.x >> 5) + (threadIdx.x >> 5);
    if (q >= B) return;

    uint64_t q0, q1, q2, q3;
    pack_row_f4(syn + (size_t)q * SL, lane, q0, q1, q2, q3);
    unsigned b0 = (unsigned)mix64(fold_hash(q0, q1, q2, q3)) & (NB - 1);

    // ---- Single-hop warp-parallel probe ----
    unsigned slot = (b0 + lane) & (NB - 1);
    unsigned s = __ldg(&g_sidx[slot]);

    // Speculative key loads on lanes 0..7 (clusters >8 are vanishingly rare);
    // the address depends only on the slot, so these issue alongside sidx.
    ulonglong2 ka, kc;
    bool spec = (lane < 8);
    if (spec) {
        const ulonglong2* kp = (const ulonglong2*)&g_skey[slot];
        ka = __ldg(kp);
        kc = __ldg(kp + 1);
    }

    unsigned empty = __ballot_sync(0xffffffffu, s == 0u);
    int fe = empty ? (__ffs(empty) - 1) : 32;

    int best = 0x7fffffff;
    if (s != 0u && lane < fe) {
        if (!spec) {   // rare dependent fallback for lanes 8..fe-1
            const ulonglong2* kp = (const ulonglong2*)&g_skey[slot];
            ka = __ldg(kp);
            kc = __ldg(kp + 1);
        }
        if (ka.x == q0 && ka.y == q1 && kc.x == q2 && kc.y == q3)
            best = (int)s - 1;                        // first match = min idx
    }
    if (fe == 32)
        best = min(best, probe_more((b0 + 32) & (NB - 1), lane, q0, q1, q2, q3));

    best = (int)__reduce_min_sync(0xffffffffu, (unsigned)best);

    // ---- Vectorized emit: 256 floats = 64 float4; 2 per lane ----
    float4* orow4 = (float4*)(out + (size_t)q * SL);
    if (best != 0x7fffffff) {
        const float4* vr = (const float4*)(tv + (size_t)best * SL);
        float4 a = __ldg(vr + lane);
        float4 c = __ldg(vr + lane + 32);
        orow4[lane]      = a;
        orow4[lane + 32] = c;
    } else {
        float4 z = make_float4(0.f, 0.f, 0.f, 0.f);
        orow4[lane]      = z;
        orow4[lane + 32] = z;
    }
}

// ---------------------------------------------------------------------------
extern "C" void kernel_launch(void* const* d_in, const int* in_sizes, int n_in,
                              void* d_out, int out_size) {
    const float* syn = (const float*)d_in[0];   // [B, 256]
    const float* tk  = (const float*)d_in[1];   // [T, 256]
    const float* tv  = (const float*)d_in[2];   // [T, 256]
    float* out = (float*)d_out;                 // [B, 256]

    int B = in_sizes[0] / SL;
    int T = in_sizes[1] / SL;

    build_table_kernel<<<(T + 7) / 8, 256>>>(tk, T);
    // 512 threads = 16 warps/block, 1 query/warp.
    lookup_kernel<<<(B + 15) / 16, 512>>>(syn, tv, out, B);
}